// round 5
// baseline (speedup 1.0000x reference)
#include <cuda_runtime.h>
#include <cuda_bf16.h>
#include <cstdint>
#include <math_constants.h>

#define NROWS   65536       // 4*2048*8 query rows
#define D       256
#define SUB     128
#define NC      1024
#define KOUT    16
#define TM      16          // rows per gemm block
#define THREADS 512
#define NEG_BIG (-CUDART_INF_F)

#define TILE_F  8192                         // 8 k x 1024 cols (floats)
#define OFF_CT  0                            // 2 x 32 KB (also reused for scores)
#define OFF_QN  (2 * TILE_F * 4)             // 65536
#define SMEM_BYTES (OFF_QN + TM * SUB * 4)   // 73728

// pre-swizzled centroids: [m][16 tiles][2048 16B-units]
__device__ float g_ct[2 * 16 * TILE_F];
__device__ float g_tv[2][NROWS * KOUT];
__device__ int   g_ti[2][NROWS * KOUT];

__device__ __forceinline__ void cp_async16(void* dst, const void* src) {
    uint32_t d32 = (uint32_t)__cvta_generic_to_shared(dst);
    asm volatile("cp.async.cg.shared.global [%0], [%1], 16;" :: "r"(d32), "l"(src));
}

// ---------------------------------------------------------------------------
// Kernel 0: rearrange C[1024][128] into swizzled k-tiled layout.
// For tile t, col c, s in {0,1}: unit u = (c*2+s) ^ ((c>>3)&7)
// holds C[c][t*8 + s*4 .. +3].
// ---------------------------------------------------------------------------
__global__ __launch_bounds__(256)
void pkr_prep(const float* __restrict__ ck, const float* __restrict__ cpk)
{
    const int m = blockIdx.x >> 4;
    const int t = blockIdx.x & 15;
    const float* C = m ? cpk : ck;
    float* dst = g_ct + m * 16 * TILE_F + t * TILE_F;
    for (int i = threadIdx.x; i < 2048; i += 256) {
        int c = i >> 1, s = i & 1;
        int u = i ^ ((i >> 4) & 7);
        *(float4*)&dst[u * 4] = *(const float4*)&C[c * SUB + t * 8 + s * 4];
    }
}

// ---------------------------------------------------------------------------
// Kernel 1: LN + per-subspace GEMM (16 x 1024 x 128) + per-row top-16
// grid = 8192: blockIdx>>1 = row tile, blockIdx&1 = subspace. 512 thr, occ 2.
// ---------------------------------------------------------------------------
__global__ __launch_bounds__(THREADS, 2)
void pkr_gemm(const float* __restrict__ q,
              const float* __restrict__ gamma,
              const float* __restrict__ beta)
{
    extern __shared__ char smraw[];
    float* ct = (float*)(smraw + OFF_CT);
    float* qn = (float*)(smraw + OFF_QN);   // [row][128] local k
    float* sc = (float*)(smraw + OFF_CT);   // aliases ct after mainloop

    const int tx   = threadIdx.x;
    const int warp = tx >> 5;
    const int lane = tx & 31;
    const int m    = blockIdx.x & 1;
    const long base = (long)(blockIdx.x >> 1) * TM;

    const float* gsrc = g_ct + m * 16 * TILE_F;

    auto prefetch = [&](int t, int buf) {
        const float* src = gsrc + t * TILE_F;
        float* dst = ct + buf * TILE_F;
        #pragma unroll
        for (int i = 0; i < 4; i++) {
            int e = (tx + THREADS * i) * 4;
            cp_async16(dst + e, src + e);
        }
        asm volatile("cp.async.commit_group;");
    };

    prefetch(0, 0);
    prefetch(1, 1);

    // ---- LayerNorm: warp w handles row w; keep our 128-half in qn
    {
        const int row = warp;
        const float* qrow = q + (base + row) * D;
        float v[8];
        float s = 0.f, s2 = 0.f;
        #pragma unroll
        for (int i = 0; i < 8; i++) {
            v[i] = qrow[lane + 32 * i];
            s  += v[i];
            s2 += v[i] * v[i];
        }
        #pragma unroll
        for (int o = 16; o; o >>= 1) {
            s  += __shfl_xor_sync(0xffffffffu, s,  o);
            s2 += __shfl_xor_sync(0xffffffffu, s2, o);
        }
        float mu  = s * (1.f / D);
        float var = s2 * (1.f / D) - mu * mu;
        float inv = rsqrtf(var + 1e-5f);
        #pragma unroll
        for (int i = 0; i < 4; i++) {
            int ig = i + 4 * m;             // d = lane + 32*ig
            int d  = lane + 32 * ig;
            qn[row * SUB + (d - m * SUB)] =
                (v[ig] - mu) * inv * gamma[d] + beta[d];
        }
    }

    // ---- GEMM: thread tile 4 rows x 8 cols over full 1024 cols
    const int c_g = tx & 127;               // cols 8*c_g .. 8*c_g+7
    const int r_g = tx >> 7;                // rows 4*r_g .. 4*r_g+3
    const int sw  = c_g & 7;

    float acc[4][8];
    #pragma unroll
    for (int r = 0; r < 4; r++)
        #pragma unroll
        for (int j = 0; j < 8; j++) acc[r][j] = 0.f;

    for (int t = 0; t < 16; t++) {
        if (t < 14) {
            asm volatile("cp.async.wait_group 1;");
        } else {
            asm volatile("cp.async.wait_group 0;");
        }
        __syncthreads();

        const float4* ctb = (const float4*)(ct + (t & 1) * TILE_F);
        const float4* qn4 = (const float4*)qn;

        #pragma unroll
        for (int s = 0; s < 2; s++) {
            const int k4 = t * 2 + s;
            float4 qv[4];
            #pragma unroll
            for (int r = 0; r < 4; r++)
                qv[r] = qn4[(4 * r_g + r) * 32 + k4];
            #pragma unroll
            for (int j = 0; j < 8; j++) {
                const int c = 8 * c_g + j;
                float4 cc = ctb[(c * 2 + s) ^ sw];
                #pragma unroll
                for (int r = 0; r < 4; r++) {
                    acc[r][j] = fmaf(qv[r].x, cc.x, acc[r][j]);
                    acc[r][j] = fmaf(qv[r].y, cc.y, acc[r][j]);
                    acc[r][j] = fmaf(qv[r].z, cc.z, acc[r][j]);
                    acc[r][j] = fmaf(qv[r].w, cc.w, acc[r][j]);
                }
            }
        }
        __syncthreads();

        if (t < 14) prefetch(t + 2, t & 1);
    }

    // ---- write scores into smem (ct buffers are dead now)
    #pragma unroll
    for (int r = 0; r < 4; r++) {
        const int row = 4 * r_g + r;
        *(float4*)&sc[row * NC + 8 * c_g] =
            make_float4(acc[r][0], acc[r][1], acc[r][2], acc[r][3]);
        *(float4*)&sc[row * NC + 8 * c_g + 4] =
            make_float4(acc[r][4], acc[r][5], acc[r][6], acc[r][7]);
    }
    __syncthreads();

    // ---- per-row top-16 of 1024 (warp w: row w), threshold scan, regs only
    {
        const int row = warp;
        float v[32];
        #pragma unroll
        for (int i = 0; i < 32; i++)
            v[i] = sc[row * NC + lane + 32 * i];

        float wv = CUDART_INF_F;    // previous winner (value)
        int   wi = -1;              // previous winner (global idx)

        long gb = (base + row) * KOUT;
        for (int r16 = 0; r16 < 16; r16++) {
            // lane-local max among elements strictly below (wv, wi)
            float best = NEG_BIG;
            int   bidx = 0;
            #pragma unroll
            for (int i = 0; i < 32; i++) {
                int  gi   = lane + 32 * i;
                bool pass = (v[i] < wv) || (v[i] == wv && gi > wi);
                if (pass && v[i] > best) { best = v[i]; bidx = gi; }
            }
            // warp reduce: value desc, index asc
            float cv = best;
            int   ci = bidx;
            #pragma unroll
            for (int o = 16; o; o >>= 1) {
                float ov = __shfl_xor_sync(0xffffffffu, cv, o);
                int   oi = __shfl_xor_sync(0xffffffffu, ci, o);
                if (ov > cv || (ov == cv && oi < ci)) { cv = ov; ci = oi; }
            }
            if (lane == 0) { g_tv[m][gb + r16] = cv; g_ti[m][gb + r16] = ci; }
            wv = cv;
            wi = ci;
        }
    }
}

// ---------------------------------------------------------------------------
// Kernel 2: joint 16x16 top-16 + output. 8 rows/block, 1 row per warp.
// ---------------------------------------------------------------------------
__global__ __launch_bounds__(256, 1)
void pkr_joint(float* __restrict__ out)
{
    __shared__ float s1v[8 * KOUT], s2v[8 * KOUT];
    __shared__ int   s1i[8 * KOUT], s2i[8 * KOUT];

    const int tx   = threadIdx.x;
    const int warp = tx >> 5;
    const int lane = tx & 31;
    const long base = (long)blockIdx.x * 8;

    if (tx < 128) {
        long g = base * KOUT + tx;
        s1v[tx] = g_tv[0][g];
        s1i[tx] = g_ti[0][g];
    } else {
        int t2 = tx - 128;
        long g = base * KOUT + t2;
        s2v[t2] = g_tv[1][g];
        s2i[t2] = g_ti[1][g];
    }
    __syncthreads();

    const int row = warp;
    float v8[8];
    #pragma unroll
    for (int u = 0; u < 8; u++) {
        int f = lane + 32 * u;
        v8[u] = s1v[row * KOUT + (f >> 4)] + s2v[row * KOUT + (f & 15)];
    }

    float wv = CUDART_INF_F;
    int   wi = -1;

    long R = base + row;
    for (int r16 = 0; r16 < 16; r16++) {
        float best = NEG_BIG;
        int   bidx = 0;
        #pragma unroll
        for (int u = 0; u < 8; u++) {
            int  f    = lane + 32 * u;
            bool pass = (v8[u] < wv) || (v8[u] == wv && f > wi);
            if (pass && v8[u] > best) { best = v8[u]; bidx = f; }
        }
        float cv = best;
        int   ci = bidx;
        #pragma unroll
        for (int o = 16; o; o >>= 1) {
            float ov = __shfl_xor_sync(0xffffffffu, cv, o);
            int   oi = __shfl_xor_sync(0xffffffffu, ci, o);
            if (ov > cv || (ov == cv && oi < ci)) { cv = ov; ci = oi; }
        }
        if (lane == 0) {
            int i16 = ci >> 4, j16 = ci & 15;
            int gidx = s1i[row * KOUT + i16] * NC + s2i[row * KOUT + j16];
            out[R * KOUT + r16]                      = (float)gidx;
            out[(long)NROWS * KOUT + R * KOUT + r16] = cv;
        }
        wv = cv;
        wi = ci;
    }
}

extern "C" void kernel_launch(void* const* d_in, const int* in_sizes, int n_in,
                              void* d_out, int out_size)
{
    const float* q     = (const float*)d_in[0];
    const float* ck    = (const float*)d_in[1];
    const float* cpk   = (const float*)d_in[2];
    const float* gamma = (const float*)d_in[3];
    const float* beta  = (const float*)d_in[4];
    float* out = (float*)d_out;

    cudaFuncSetAttribute(pkr_gemm,
                         cudaFuncAttributeMaxDynamicSharedMemorySize, SMEM_BYTES);

    pkr_prep<<<32, 256>>>(ck, cpk);
    pkr_gemm<<<(NROWS / TM) * 2, THREADS, SMEM_BYTES>>>(q, gamma, beta);
    pkr_joint<<<NROWS / 8, 256>>>(out);
}

// round 7
// speedup vs baseline: 1.3843x; 1.3843x over previous
#include <cuda_runtime.h>
#include <cuda_bf16.h>
#include <cstdint>

#define NROWS   65536       // 4*2048*8 query rows
#define D       256
#define SUB     128
#define NC      1024
#define KOUT    16
#define TM      16          // rows per gemm block
#define THREADS 512

#define TILE_F  8192                         // 8 k x 1024 cols (floats)
#define OFF_CT  0                            // 2 x 32 KB
#define OFF_QN  (2 * TILE_F * 4)             // 65536
#define OFF_SC  (OFF_QN + TM * SUB * 4)      // 73728
#define SMEM_BYTES (OFF_SC + TM * NC * 4)    // 139264

// pre-swizzled centroids: [m][16 tiles][2048 16B-units]
__device__ float g_ct[2 * 16 * TILE_F];
__device__ float g_tv[2][NROWS * KOUT];
__device__ int   g_ti[2][NROWS * KOUT];

__device__ __forceinline__ void cp_async16(void* dst, const void* src) {
    uint32_t d32 = (uint32_t)__cvta_generic_to_shared(dst);
    asm volatile("cp.async.cg.shared.global [%0], [%1], 16;" :: "r"(d32), "l"(src));
}

// order-preserving float<->uint bijection
__device__ __forceinline__ uint32_t fmono(float f) {
    uint32_t u = __float_as_uint(f);
    return u ^ ((uint32_t)((int32_t)u >> 31) | 0x80000000u);
}
__device__ __forceinline__ float fmono_inv(uint32_t m) {
    uint32_t u = (m & 0x80000000u) ? (m ^ 0x80000000u) : ~m;
    return __uint_as_float(u);
}
__device__ __forceinline__ uint32_t um(uint32_t a, uint32_t b) { return a > b ? a : b; }

// ---------------------------------------------------------------------------
// Kernel 0: rearrange C[1024][128] into swizzled k-tiled layout.
// ---------------------------------------------------------------------------
__global__ __launch_bounds__(256)
void pkr_prep(const float* __restrict__ ck, const float* __restrict__ cpk)
{
    const int m = blockIdx.x >> 4;
    const int t = blockIdx.x & 15;
    const float* C = m ? cpk : ck;
    float* dst = g_ct + m * 16 * TILE_F + t * TILE_F;
    for (int i = threadIdx.x; i < 2048; i += 256) {
        int c = i >> 1, s = i & 1;
        int u = i ^ ((i >> 4) & 7);
        *(float4*)&dst[u * 4] = *(const float4*)&C[c * SUB + t * 8 + s * 4];
    }
}

// ---------------------------------------------------------------------------
// Kernel 1: LN + per-subspace GEMM (16 x 1024 x 128) + per-row top-16
// grid = 8192: blockIdx>>1 = row tile, blockIdx&1 = subspace. 512 threads.
// ---------------------------------------------------------------------------
__global__ __launch_bounds__(THREADS, 1)
void pkr_gemm(const float* __restrict__ q,
              const float* __restrict__ gamma,
              const float* __restrict__ beta)
{
    extern __shared__ char smraw[];
    float* ct = (float*)(smraw + OFF_CT);
    float* qn = (float*)(smraw + OFF_QN);   // [row][128] local k
    float* sc = (float*)(smraw + OFF_SC);

    const int tx   = threadIdx.x;
    const int warp = tx >> 5;
    const int lane = tx & 31;
    const int m    = blockIdx.x & 1;
    const long base = (long)(blockIdx.x >> 1) * TM;

    const float* gsrc = g_ct + m * 16 * TILE_F;

    auto prefetch = [&](int t, int buf) {
        const float* src = gsrc + t * TILE_F;
        float* dst = ct + buf * TILE_F;
        #pragma unroll
        for (int i = 0; i < 4; i++) {
            int e = (tx + THREADS * i) * 4;
            cp_async16(dst + e, src + e);
        }
        asm volatile("cp.async.commit_group;");
    };

    prefetch(0, 0);
    prefetch(1, 1);

    // ---- LayerNorm: warp w handles row w; keep our 128-half in qn
    {
        const int row = warp;
        const float* qrow = q + (base + row) * D;
        float v[8];
        float s = 0.f, s2 = 0.f;
        #pragma unroll
        for (int i = 0; i < 8; i++) {
            v[i] = qrow[lane + 32 * i];
            s  += v[i];
            s2 += v[i] * v[i];
        }
        #pragma unroll
        for (int o = 16; o; o >>= 1) {
            s  += __shfl_xor_sync(0xffffffffu, s,  o);
            s2 += __shfl_xor_sync(0xffffffffu, s2, o);
        }
        float mu  = s * (1.f / D);
        float var = s2 * (1.f / D) - mu * mu;
        float inv = rsqrtf(var + 1e-5f);
        #pragma unroll
        for (int i = 0; i < 4; i++) {
            int ig = i + 4 * m;             // d = lane + 32*ig
            int d  = lane + 32 * ig;
            qn[row * SUB + (d - m * SUB)] =
                (v[ig] - mu) * inv * gamma[d] + beta[d];
        }
    }

    // ---- GEMM: thread tile 4 rows x 8 cols over full 1024 cols
    const int c_g = tx & 127;               // cols 8*c_g .. 8*c_g+7
    const int r_g = tx >> 7;                // rows 4*r_g .. 4*r_g+3
    const int sw  = c_g & 7;

    float acc[4][8];
    #pragma unroll
    for (int r = 0; r < 4; r++)
        #pragma unroll
        for (int j = 0; j < 8; j++) acc[r][j] = 0.f;

    for (int t = 0; t < 16; t++) {
        if (t < 14) {
            asm volatile("cp.async.wait_group 1;");
        } else {
            asm volatile("cp.async.wait_group 0;");
        }
        __syncthreads();

        const float4* ctb = (const float4*)(ct + (t & 1) * TILE_F);
        const float4* qn4 = (const float4*)qn;

        #pragma unroll
        for (int s = 0; s < 2; s++) {
            const int k4 = t * 2 + s;
            float4 qv[4];
            #pragma unroll
            for (int r = 0; r < 4; r++)
                qv[r] = qn4[(4 * r_g + r) * 32 + k4];
            #pragma unroll
            for (int j = 0; j < 8; j++) {
                const int c = 8 * c_g + j;
                float4 cc = ctb[(c * 2 + s) ^ sw];
                #pragma unroll
                for (int r = 0; r < 4; r++) {
                    acc[r][j] = fmaf(qv[r].x, cc.x, acc[r][j]);
                    acc[r][j] = fmaf(qv[r].y, cc.y, acc[r][j]);
                    acc[r][j] = fmaf(qv[r].z, cc.z, acc[r][j]);
                    acc[r][j] = fmaf(qv[r].w, cc.w, acc[r][j]);
                }
            }
        }
        __syncthreads();

        if (t < 14) prefetch(t + 2, t & 1);
    }

    // ---- write scores
    #pragma unroll
    for (int r = 0; r < 4; r++) {
        const int row = 4 * r_g + r;
        *(float4*)&sc[row * NC + 8 * c_g] =
            make_float4(acc[r][0], acc[r][1], acc[r][2], acc[r][3]);
        *(float4*)&sc[row * NC + 8 * c_g + 4] =
            make_float4(acc[r][4], acc[r][5], acc[r][6], acc[r][7]);
    }
    __syncthreads();

    // ---- per-row top-16 of 1024: tournament with exact min-index ties
    {
        const int row = warp;
        uint32_t mv[32];
        #pragma unroll
        for (int i = 0; i < 32; i++)
            mv[i] = fmono(sc[row * NC + lane + 32 * i]);

        uint32_t g0, g1, g2, g3;
        #define GMAX8(B) um(um(um(mv[B],mv[B+1]),um(mv[B+2],mv[B+3])), \
                            um(um(mv[B+4],mv[B+5]),um(mv[B+6],mv[B+7])))
        g0 = GMAX8(0); g1 = GMAX8(8); g2 = GMAX8(16); g3 = GMAX8(24);

        long gb = (base + row) * KOUT;
        for (int r16 = 0; r16 < 16; r16++) {
            uint32_t lm = um(um(g0, g1), um(g2, g3));
            uint32_t wm = __reduce_max_sync(0xffffffffu, lm);
            uint32_t cand = 0xffffffffu;
            int e = 0;
            if (lm == wm) {
                // first matching group (ascending) holds this lane's min index
                if (g0 == wm) {
                    #pragma unroll
                    for (int j = 7; j >= 0; j--) if (mv[j] == wm) e = j;
                } else if (g1 == wm) {
                    e = 8;
                    #pragma unroll
                    for (int j = 15; j >= 8; j--) if (mv[j] == wm) e = j;
                } else if (g2 == wm) {
                    e = 16;
                    #pragma unroll
                    for (int j = 23; j >= 16; j--) if (mv[j] == wm) e = j;
                } else {
                    e = 24;
                    #pragma unroll
                    for (int j = 31; j >= 24; j--) if (mv[j] == wm) e = j;
                }
                cand = (uint32_t)(lane + 32 * e);
            }
            uint32_t gidx = __reduce_min_sync(0xffffffffu, cand);
            if (cand == gidx) {
                // remove element e (static per-group) and rebuild that group max
                if (e < 8) {
                    #pragma unroll
                    for (int j = 0; j < 8; j++) mv[j] = (j == e) ? 0u : mv[j];
                    g0 = GMAX8(0);
                } else if (e < 16) {
                    #pragma unroll
                    for (int j = 8; j < 16; j++) mv[j] = (j == e) ? 0u : mv[j];
                    g1 = GMAX8(8);
                } else if (e < 24) {
                    #pragma unroll
                    for (int j = 16; j < 24; j++) mv[j] = (j == e) ? 0u : mv[j];
                    g2 = GMAX8(16);
                } else {
                    #pragma unroll
                    for (int j = 24; j < 32; j++) mv[j] = (j == e) ? 0u : mv[j];
                    g3 = GMAX8(24);
                }
            }
            if (lane == 0) {
                g_tv[m][gb + r16] = fmono_inv(wm);
                g_ti[m][gb + r16] = (int)gidx;
            }
        }
        #undef GMAX8
    }
}

// ---------------------------------------------------------------------------
// Kernel 2: joint 16x16 top-16 + output. 8 rows/block, 1 row per warp.
// ---------------------------------------------------------------------------
__global__ __launch_bounds__(256, 1)
void pkr_joint(float* __restrict__ out)
{
    __shared__ float s1v[8 * KOUT], s2v[8 * KOUT];
    __shared__ int   s1i[8 * KOUT], s2i[8 * KOUT];

    const int tx   = threadIdx.x;
    const int warp = tx >> 5;
    const int lane = tx & 31;
    const long base = (long)blockIdx.x * 8;

    if (tx < 128) {
        long g = base * KOUT + tx;
        s1v[tx] = g_tv[0][g];
        s1i[tx] = g_ti[0][g];
    } else {
        int t2 = tx - 128;
        long g = base * KOUT + t2;
        s2v[t2] = g_tv[1][g];
        s2i[t2] = g_ti[1][g];
    }
    __syncthreads();

    const int row = warp;
    uint32_t mv[8];
    #pragma unroll
    for (int u = 0; u < 8; u++) {
        int f = lane + 32 * u;
        mv[u] = fmono(s1v[row * KOUT + (f >> 4)] + s2v[row * KOUT + (f & 15)]);
    }

    long R = base + row;
    for (int r16 = 0; r16 < 16; r16++) {
        uint32_t lm = um(um(um(mv[0], mv[1]), um(mv[2], mv[3])),
                         um(um(mv[4], mv[5]), um(mv[6], mv[7])));
        uint32_t wm = __reduce_max_sync(0xffffffffu, lm);
        uint32_t cand = 0xffffffffu;
        int e = 0;
        if (lm == wm) {
            #pragma unroll
            for (int j = 7; j >= 0; j--) if (mv[j] == wm) e = j;
            cand = (uint32_t)(lane + 32 * e);
        }
        uint32_t f = __reduce_min_sync(0xffffffffu, cand);
        if (cand == f) {
            #pragma unroll
            for (int j = 0; j < 8; j++) mv[j] = (j == e) ? 0u : mv[j];
        }
        if (lane == 0) {
            int i16 = (int)(f >> 4) & 15;   // f = i16*16 + j16 (flat joint idx)
            int j16 = (int)(f & 15);
            int gidx = s1i[row * KOUT + i16] * NC + s2i[row * KOUT + j16];
            out[R * KOUT + r16]                      = (float)gidx;
            out[(long)NROWS * KOUT + R * KOUT + r16] = fmono_inv(wm);
        }
    }
}

extern "C" void kernel_launch(void* const* d_in, const int* in_sizes, int n_in,
                              void* d_out, int out_size)
{
    const float* q     = (const float*)d_in[0];
    const float* ck    = (const float*)d_in[1];
    const float* cpk   = (const float*)d_in[2];
    const float* gamma = (const float*)d_in[3];
    const float* beta  = (const float*)d_in[4];
    float* out = (float*)d_out;

    cudaFuncSetAttribute(pkr_gemm,
                         cudaFuncAttributeMaxDynamicSharedMemorySize, SMEM_BYTES);

    pkr_prep<<<32, 256>>>(ck, cpk);
    pkr_gemm<<<(NROWS / TM) * 2, THREADS, SMEM_BYTES>>>(q, gamma, beta);
    pkr_joint<<<NROWS / 8, 256>>>(out);
}

// round 8
// speedup vs baseline: 1.4262x; 1.0303x over previous
#include <cuda_runtime.h>
#include <cuda_bf16.h>
#include <cstdint>

#define NROWS   65536       // 4*2048*8 query rows
#define D       256
#define SUB     128
#define NC      1024
#define KOUT    16
#define TM      32          // rows per gemm block
#define THREADS 1024

#define TILE_F  8192                         // 8 k x 1024 cols (floats)
#define OFF_CT  0                            // 2 x 32 KB
#define OFF_QN  (2 * TILE_F * 4)             // 65536
#define OFF_SC  (OFF_QN + TM * SUB * 4)      // 81920
#define SMEM_BYTES (OFF_SC + TM * NC * 4)    // 212992

// pre-swizzled centroids: [m][16 tiles][2048 16B-units]
__device__ float g_ct[2 * 16 * TILE_F];
__device__ float g_tv[2][NROWS * KOUT];
__device__ int   g_ti[2][NROWS * KOUT];

__device__ __forceinline__ void cp_async16(void* dst, const void* src) {
    uint32_t d32 = (uint32_t)__cvta_generic_to_shared(dst);
    asm volatile("cp.async.cg.shared.global [%0], [%1], 16;" :: "r"(d32), "l"(src));
}

// order-preserving float<->uint bijection
__device__ __forceinline__ uint32_t fmono(float f) {
    uint32_t u = __float_as_uint(f);
    return u ^ ((uint32_t)((int32_t)u >> 31) | 0x80000000u);
}
__device__ __forceinline__ float fmono_inv(uint32_t m) {
    uint32_t u = (m & 0x80000000u) ? (m ^ 0x80000000u) : ~m;
    return __uint_as_float(u);
}
__device__ __forceinline__ uint32_t um(uint32_t a, uint32_t b) { return a > b ? a : b; }

// ---------------------------------------------------------------------------
// Kernel 0: rearrange C[1024][128] into swizzled k-tiled layout.
// ---------------------------------------------------------------------------
__global__ __launch_bounds__(256)
void pkr_prep(const float* __restrict__ ck, const float* __restrict__ cpk)
{
    const int m = blockIdx.x >> 4;
    const int t = blockIdx.x & 15;
    const float* C = m ? cpk : ck;
    float* dst = g_ct + m * 16 * TILE_F + t * TILE_F;
    for (int i = threadIdx.x; i < 2048; i += 256) {
        int c = i >> 1, s = i & 1;
        int u = i ^ ((i >> 4) & 7);
        *(float4*)&dst[u * 4] = *(const float4*)&C[c * SUB + t * 8 + s * 4];
    }
}

// ---------------------------------------------------------------------------
// Kernel 1: LN + per-subspace GEMM (32 x 1024 x 128) + per-row top-16
// grid = 4096: blockIdx>>1 = row tile, blockIdx&1 = subspace. 1024 threads.
// ---------------------------------------------------------------------------
__global__ __launch_bounds__(THREADS, 1)
void pkr_gemm(const float* __restrict__ q,
              const float* __restrict__ gamma,
              const float* __restrict__ beta)
{
    extern __shared__ char smraw[];
    float* ct = (float*)(smraw + OFF_CT);
    float* qn = (float*)(smraw + OFF_QN);   // [row][128] local k
    float* sc = (float*)(smraw + OFF_SC);

    const int tx   = threadIdx.x;
    const int warp = tx >> 5;
    const int lane = tx & 31;
    const int m    = blockIdx.x & 1;
    const long base = (long)(blockIdx.x >> 1) * TM;

    const float* gsrc = g_ct + m * 16 * TILE_F;

    auto prefetch = [&](int t, int buf) {
        const float* src = gsrc + t * TILE_F;
        float* dst = ct + buf * TILE_F;
        #pragma unroll
        for (int i = 0; i < 2; i++) {
            int e = (tx + THREADS * i) * 4;
            cp_async16(dst + e, src + e);
        }
        asm volatile("cp.async.commit_group;");
    };

    prefetch(0, 0);
    prefetch(1, 1);

    // ---- LayerNorm: warp w handles row w (32 rows); keep our 128-half
    {
        const int row = warp;
        const float* qrow = q + (base + row) * D;
        float v[8];
        float s = 0.f, s2 = 0.f;
        #pragma unroll
        for (int i = 0; i < 8; i++) {
            v[i] = qrow[lane + 32 * i];
            s  += v[i];
            s2 += v[i] * v[i];
        }
        #pragma unroll
        for (int o = 16; o; o >>= 1) {
            s  += __shfl_xor_sync(0xffffffffu, s,  o);
            s2 += __shfl_xor_sync(0xffffffffu, s2, o);
        }
        float mu  = s * (1.f / D);
        float var = s2 * (1.f / D) - mu * mu;
        float inv = rsqrtf(var + 1e-5f);
        #pragma unroll
        for (int i = 0; i < 4; i++) {
            int ig = i + 4 * m;             // d = lane + 32*ig
            int d  = lane + 32 * ig;
            qn[row * SUB + (d - m * SUB)] =
                (v[ig] - mu) * inv * gamma[d] + beta[d];
        }
    }

    // ---- GEMM: thread tile 4 rows x 8 cols over full 1024 cols
    const int c_g = tx & 127;               // cols 8*c_g .. 8*c_g+7
    const int r_g = tx >> 7;                // rows 4*r_g .. 4*r_g+3 (8 groups)
    const int sw  = c_g & 7;

    float acc[4][8];
    #pragma unroll
    for (int r = 0; r < 4; r++)
        #pragma unroll
        for (int j = 0; j < 8; j++) acc[r][j] = 0.f;

    for (int t = 0; t < 16; t++) {
        if (t < 14) {
            asm volatile("cp.async.wait_group 1;");
        } else {
            asm volatile("cp.async.wait_group 0;");
        }
        __syncthreads();

        const float4* ctb = (const float4*)(ct + (t & 1) * TILE_F);
        const float4* qn4 = (const float4*)qn;

        #pragma unroll
        for (int s = 0; s < 2; s++) {
            const int k4 = t * 2 + s;
            float4 qv[4];
            #pragma unroll
            for (int r = 0; r < 4; r++)
                qv[r] = qn4[(4 * r_g + r) * 32 + k4];
            #pragma unroll
            for (int j = 0; j < 8; j++) {
                const int c = 8 * c_g + j;
                float4 cc = ctb[(c * 2 + s) ^ sw];
                #pragma unroll
                for (int r = 0; r < 4; r++) {
                    acc[r][j] = fmaf(qv[r].x, cc.x, acc[r][j]);
                    acc[r][j] = fmaf(qv[r].y, cc.y, acc[r][j]);
                    acc[r][j] = fmaf(qv[r].z, cc.z, acc[r][j]);
                    acc[r][j] = fmaf(qv[r].w, cc.w, acc[r][j]);
                }
            }
        }
        __syncthreads();

        if (t < 14) prefetch(t + 2, t & 1);
    }

    // ---- write scores
    #pragma unroll
    for (int r = 0; r < 4; r++) {
        const int row = 4 * r_g + r;
        *(float4*)&sc[row * NC + 8 * c_g] =
            make_float4(acc[r][0], acc[r][1], acc[r][2], acc[r][3]);
        *(float4*)&sc[row * NC + 8 * c_g + 4] =
            make_float4(acc[r][4], acc[r][5], acc[r][6], acc[r][7]);
    }
    __syncthreads();

    // ---- per-row top-16 of 1024: tournament with exact min-index ties
    {
        const int row = warp;
        uint32_t mv[32];
        #pragma unroll
        for (int i = 0; i < 32; i++)
            mv[i] = fmono(sc[row * NC + lane + 32 * i]);

        uint32_t g0, g1, g2, g3;
        #define GMAX8(B) um(um(um(mv[B],mv[B+1]),um(mv[B+2],mv[B+3])), \
                            um(um(mv[B+4],mv[B+5]),um(mv[B+6],mv[B+7])))
        g0 = GMAX8(0); g1 = GMAX8(8); g2 = GMAX8(16); g3 = GMAX8(24);

        long gb = (base + row) * KOUT;
        for (int r16 = 0; r16 < 16; r16++) {
            uint32_t lm = um(um(g0, g1), um(g2, g3));
            uint32_t wm = __reduce_max_sync(0xffffffffu, lm);
            uint32_t cand = 0xffffffffu;
            int e = 0;
            if (lm == wm) {
                if (g0 == wm) {
                    #pragma unroll
                    for (int j = 7; j >= 0; j--) if (mv[j] == wm) e = j;
                } else if (g1 == wm) {
                    e = 8;
                    #pragma unroll
                    for (int j = 15; j >= 8; j--) if (mv[j] == wm) e = j;
                } else if (g2 == wm) {
                    e = 16;
                    #pragma unroll
                    for (int j = 23; j >= 16; j--) if (mv[j] == wm) e = j;
                } else {
                    e = 24;
                    #pragma unroll
                    for (int j = 31; j >= 24; j--) if (mv[j] == wm) e = j;
                }
                cand = (uint32_t)(lane + 32 * e);
            }
            uint32_t gidx = __reduce_min_sync(0xffffffffu, cand);
            if (cand == gidx) {
                if (e < 8) {
                    #pragma unroll
                    for (int j = 0; j < 8; j++) mv[j] = (j == e) ? 0u : mv[j];
                    g0 = GMAX8(0);
                } else if (e < 16) {
                    #pragma unroll
                    for (int j = 8; j < 16; j++) mv[j] = (j == e) ? 0u : mv[j];
                    g1 = GMAX8(8);
                } else if (e < 24) {
                    #pragma unroll
                    for (int j = 16; j < 24; j++) mv[j] = (j == e) ? 0u : mv[j];
                    g2 = GMAX8(16);
                } else {
                    #pragma unroll
                    for (int j = 24; j < 32; j++) mv[j] = (j == e) ? 0u : mv[j];
                    g3 = GMAX8(24);
                }
            }
            if (lane == 0) {
                g_tv[m][gb + r16] = fmono_inv(wm);
                g_ti[m][gb + r16] = (int)gidx;
            }
        }
        #undef GMAX8
    }
}

// ---------------------------------------------------------------------------
// Kernel 2: joint 16x16 top-16 + output. 8 rows/block, 1 row per warp.
// ---------------------------------------------------------------------------
__global__ __launch_bounds__(256, 1)
void pkr_joint(float* __restrict__ out)
{
    __shared__ float s1v[8 * KOUT], s2v[8 * KOUT];
    __shared__ int   s1i[8 * KOUT], s2i[8 * KOUT];

    const int tx   = threadIdx.x;
    const int warp = tx >> 5;
    const int lane = tx & 31;
    const long base = (long)blockIdx.x * 8;

    if (tx < 128) {
        long g = base * KOUT + tx;
        s1v[tx] = g_tv[0][g];
        s1i[tx] = g_ti[0][g];
    } else {
        int t2 = tx - 128;
        long g = base * KOUT + t2;
        s2v[t2] = g_tv[1][g];
        s2i[t2] = g_ti[1][g];
    }
    __syncthreads();

    const int row = warp;
    uint32_t mv[8];
    #pragma unroll
    for (int u = 0; u < 8; u++) {
        int f = lane + 32 * u;
        mv[u] = fmono(s1v[row * KOUT + (f >> 4)] + s2v[row * KOUT + (f & 15)]);
    }

    long R = base + row;
    for (int r16 = 0; r16 < 16; r16++) {
        uint32_t lm = um(um(um(mv[0], mv[1]), um(mv[2], mv[3])),
                         um(um(mv[4], mv[5]), um(mv[6], mv[7])));
        uint32_t wm = __reduce_max_sync(0xffffffffu, lm);
        uint32_t cand = 0xffffffffu;
        int e = 0;
        if (lm == wm) {
            #pragma unroll
            for (int j = 7; j >= 0; j--) if (mv[j] == wm) e = j;
            cand = (uint32_t)(lane + 32 * e);
        }
        uint32_t f = __reduce_min_sync(0xffffffffu, cand);
        if (cand == f) {
            #pragma unroll
            for (int j = 0; j < 8; j++) mv[j] = (j == e) ? 0u : mv[j];
        }
        if (lane == 0) {
            int i16 = (int)(f >> 4) & 15;   // f = i16*16 + j16 (flat joint idx)
            int j16 = (int)(f & 15);
            int gidx = s1i[row * KOUT + i16] * NC + s2i[row * KOUT + j16];
            out[R * KOUT + r16]                      = (float)gidx;
            out[(long)NROWS * KOUT + R * KOUT + r16] = fmono_inv(wm);
        }
    }
}

extern "C" void kernel_launch(void* const* d_in, const int* in_sizes, int n_in,
                              void* d_out, int out_size)
{
    const float* q     = (const float*)d_in[0];
    const float* ck    = (const float*)d_in[1];
    const float* cpk   = (const float*)d_in[2];
    const float* gamma = (const float*)d_in[3];
    const float* beta  = (const float*)d_in[4];
    float* out = (float*)d_out;

    cudaFuncSetAttribute(pkr_gemm,
                         cudaFuncAttributeMaxDynamicSharedMemorySize, SMEM_BYTES);

    pkr_prep<<<32, 256>>>(ck, cpk);
    pkr_gemm<<<(NROWS / TM) * 2, THREADS, SMEM_BYTES>>>(q, gamma, beta);
    pkr_joint<<<NROWS / 8, 256>>>(out);
}